// round 11
// baseline (speedup 1.0000x reference)
#include <cuda_runtime.h>
#include <cuda.h>
#include <cuda_bf16.h>
#include <math.h>
#include <stdint.h>

// ===========================================================================
// R10: int8 2-slice (Ozaki) GEMM on IMMA m16n8k32 (2x legacy-HMMA rate).
// v ~ (s/127)*(q1 + q0/254) per row; C = sA*sB/127^2 * (hh + cross/254).
// TMA + SWIZZLE_64B + ldmatrix addressing identical to the bf16 engine
// (128x64 int8 tile == 128x32 bf16 tile, both 64B rows).
// ===========================================================================

#define TILE_B 8192              // one 128x64 int8 tile (bytes)
#define STAGE_B 32768            // A1,A0,B1,B0
#define NSTG 5
#define SMEM_TOT (1024 + 1024 + NSTG * STAGE_B)

__device__ __forceinline__ uint32_t smem_u32(const void* p) {
    uint32_t a;
    asm("{ .reg .u64 t; cvta.to.shared.u64 t, %1; cvt.u32.u64 %0, t; }" : "=r"(a) : "l"(p));
    return a;
}
#define MBARRIER_INIT(a, c) \
    asm volatile("mbarrier.init.shared.b64 [%0], %1;" :: "r"((uint32_t)(a)), "r"((uint32_t)(c)) : "memory")
#define MBARRIER_EXPECT_TX(a, b) \
    asm volatile("mbarrier.arrive.expect_tx.shared.b64 _, [%0], %1;" :: "r"((uint32_t)(a)), "r"((uint32_t)(b)) : "memory")
#define MBARRIER_WAIT_PARITY(a, p) do { \
    uint32_t _m = (uint32_t)(a), _p = (uint32_t)(p), _d; \
    asm volatile("{\n\t.reg .pred q;\n\t" \
        "mbarrier.try_wait.parity.acquire.cta.shared::cta.b64 q, [%1], %2;\n\t" \
        "selp.b32 %0, 1, 0, q;\n\t}" : "=r"(_d) : "r"(_m), "r"(_p) : "memory"); \
    if (!_d) { \
        asm volatile("{\n\t.reg .pred Q;\n\t" \
            "WL_%=:\n\t" \
            "mbarrier.try_wait.parity.acquire.cta.shared::cta.b64 Q, [%0], %1, 0x989680;\n\t" \
            "@Q bra.uni WD_%=;\n\t" \
            "bra.uni WL_%=;\n\t" \
            "WD_%=:\n\t}" :: "r"(_m), "r"(_p) : "memory"); \
    } \
} while (0)
#define TMA_LOAD_3D(sa, tm, cx, cy, cz, mb) \
    asm volatile("cp.async.bulk.tensor.3d.shared::cta.global.tile.mbarrier::complete_tx::bytes " \
        "[%0], [%1, {%2, %3, %4}], [%5];" \
        :: "r"((uint32_t)(sa)), "l"(tm), "r"((int32_t)(cx)), "r"((int32_t)(cy)), \
           "r"((int32_t)(cz)), "r"((uint32_t)(mb)) : "memory")
#define LDSM4(R, a) \
    asm volatile("ldmatrix.sync.aligned.m8n8.x4.shared.b16 {%0,%1,%2,%3}, [%4];" \
        : "=r"((R)[0]), "=r"((R)[1]), "=r"((R)[2]), "=r"((R)[3]) : "r"(a))

__device__ __forceinline__ void mma_s8(int* c, const uint32_t* a, uint32_t b0, uint32_t b1) {
    asm volatile(
        "mma.sync.aligned.m16n8k32.row.col.s32.s8.s8.s32 "
        "{%0,%1,%2,%3}, {%4,%5,%6,%7}, {%8,%9}, {%0,%1,%2,%3};"
        : "+r"(c[0]), "+r"(c[1]), "+r"(c[2]), "+r"(c[3])
        : "r"(a[0]), "r"(a[1]), "r"(a[2]), "r"(a[3]), "r"(b0), "r"(b1));
}

// 16B XOR swizzle within a [rows x 64B] tile (== TMA SWIZZLE_64B).
__device__ __forceinline__ uint32_t sw(int row, int col16) {
    return (uint32_t)(row * 64 + ((col16 ^ ((row >> 1) & 3)) << 4));
}

// EPI 0: Cf = scaled value.  EPI 1: Cf = OTH * silu(scaled value).
template <int EPI>
__global__ __launch_bounds__(512, 1) void gemm_i8(
    const __grid_constant__ CUtensorMap tA1, const __grid_constant__ CUtensorMap tA0,
    const __grid_constant__ CUtensorMap tB1, const __grid_constant__ CUtensorMap tB0,
    float* __restrict__ Cf, const float* __restrict__ OTH,
    const float* __restrict__ sA, const float* __restrict__ sB,
    int M, int N, int K)
{
    extern __shared__ char smem[];
    const uint32_t sb0 = smem_u32(smem);
    const uint32_t sb = (sb0 + 1023) & ~1023u;
    const int tid = threadIdx.x;

    // ---- L2-friendly raster (GROUP_M = 16) ----
    const int gn = gridDim.x, gm = gridDim.y;
    const int bid = blockIdx.y * gn + blockIdx.x;
    const int npg = 16 * gn;
    const int gid = bid / npg;
    const int fm = gid * 16;
    const int gs = (gm - fm < 16) ? (gm - fm) : 16;
    const int bm = (fm + (bid % gs)) * 128;
    const int bn = ((bid % npg) / gs) * 128;

    const int w = tid >> 5, lane = tid & 31;
    const int wm = (w >> 2) * 32, wn = (w & 3) * 32;
    const int jj = lane >> 3, rr = lane & 7;
    const int aR = (jj & 1) * 8 + rr, aC16 = jj >> 1;
    const int bR = (jj >> 1) * 8 + rr, bC16 = jj & 1;

    const uint32_t bars = sb;
    const uint32_t stg0 = sb + 1024;

    if (tid == 0)
        for (int s = 0; s < NSTG; s++) MBARRIER_INIT(bars + s * 8, 1);
    __syncthreads();

    const int nst = K / 64;

    if (tid == 0) {
#pragma unroll
        for (int s = 0; s < NSTG; s++) {
            const uint32_t bar = bars + s * 8;
            const uint32_t stb = stg0 + s * STAGE_B;
            const int k0 = s * 64;
            MBARRIER_EXPECT_TX(bar, STAGE_B);
            TMA_LOAD_3D(stb,              &tA1, k0, bm, 0, bar);
            TMA_LOAD_3D(stb + TILE_B,     &tA0, k0, bm, 0, bar);
            TMA_LOAD_3D(stb + 2 * TILE_B, &tB1, k0, bn, 0, bar);
            TMA_LOAD_3D(stb + 3 * TILE_B, &tB0, k0, bn, 0, bar);
        }
    }

    int acc1[2][4][4], acc2[2][4][4];
#pragma unroll
    for (int mi = 0; mi < 2; mi++)
#pragma unroll
        for (int q = 0; q < 4; q++)
#pragma unroll
            for (int r = 0; r < 4; r++) { acc1[mi][q][r] = 0; acc2[mi][q][r] = 0; }

    for (int t = 0; t < nst; t++) {
        const int buf = t % NSTG;
        MBARRIER_WAIT_PARITY(bars + buf * 8, (t / NSTG) & 1);
        const uint32_t stb = stg0 + (uint32_t)buf * STAGE_B;

#pragma unroll
        for (int ks = 0; ks < 2; ks++) {
            uint32_t a1f[2][4], bf[2][4], a0f[2][4];
            // A1 frags (m32)
#pragma unroll
            for (int mi = 0; mi < 2; mi++)
                LDSM4(a1f[mi], stb + sw(wm + mi * 16 + aR, ks * 2 + aC16));
            // B1 frags (n32)
#pragma unroll
            for (int p = 0; p < 2; p++)
                LDSM4(bf[p], stb + 2 * TILE_B + sw(wn + p * 16 + bR, ks * 2 + bC16));
            // hh -> acc1
#pragma unroll
            for (int mi = 0; mi < 2; mi++)
#pragma unroll
                for (int q = 0; q < 4; q++)
                    mma_s8(acc1[mi][q], a1f[mi], bf[q >> 1][(q & 1) * 2], bf[q >> 1][(q & 1) * 2 + 1]);
            // A0 frags
#pragma unroll
            for (int mi = 0; mi < 2; mi++)
                LDSM4(a0f[mi], stb + TILE_B + sw(wm + mi * 16 + aR, ks * 2 + aC16));
            // a0*b1 -> acc2
#pragma unroll
            for (int mi = 0; mi < 2; mi++)
#pragma unroll
                for (int q = 0; q < 4; q++)
                    mma_s8(acc2[mi][q], a0f[mi], bf[q >> 1][(q & 1) * 2], bf[q >> 1][(q & 1) * 2 + 1]);
            // B0 frags (overwrite bf)
#pragma unroll
            for (int p = 0; p < 2; p++)
                LDSM4(bf[p], stb + 3 * TILE_B + sw(wn + p * 16 + bR, ks * 2 + bC16));
            // a1*b0 -> acc2
#pragma unroll
            for (int mi = 0; mi < 2; mi++)
#pragma unroll
                for (int q = 0; q < 4; q++)
                    mma_s8(acc2[mi][q], a1f[mi], bf[q >> 1][(q & 1) * 2], bf[q >> 1][(q & 1) * 2 + 1]);
        }

        __syncthreads();
        if (t + NSTG < nst && tid == 0) {
            const uint32_t bar = bars + buf * 8;
            const int k0 = (t + NSTG) * 64;
            MBARRIER_EXPECT_TX(bar, STAGE_B);
            TMA_LOAD_3D(stb,              &tA1, k0, bm, 0, bar);
            TMA_LOAD_3D(stb + TILE_B,     &tA0, k0, bm, 0, bar);
            TMA_LOAD_3D(stb + 2 * TILE_B, &tB1, k0, bn, 0, bar);
            TMA_LOAD_3D(stb + 3 * TILE_B, &tB0, k0, bn, 0, bar);
        }
    }

    // ---- epilogue: apply row/col scales ----
    const float i127 = 1.0f / 127.0f, i254 = 1.0f / 254.0f;
#pragma unroll
    for (int mi = 0; mi < 2; mi++) {
        const int r0 = bm + wm + mi * 16 + (lane >> 2);
        const float sa0 = sA[r0] * i127;
        const float sa8 = sA[r0 + 8] * i127;
#pragma unroll
        for (int q = 0; q < 4; q++) {
            const int col = bn + wn + q * 8 + (lane & 3) * 2;
            const float2 sc = *(const float2*)(sB + col);
            const float sb_x = sc.x * i127, sb_y = sc.y * i127;
            const size_t o0 = (size_t)r0 * N + col;
            const size_t o1 = (size_t)(r0 + 8) * N + col;
            float f0 = (float)acc1[mi][q][0] + (float)acc2[mi][q][0] * i254;
            float f1 = (float)acc1[mi][q][1] + (float)acc2[mi][q][1] * i254;
            float f2 = (float)acc1[mi][q][2] + (float)acc2[mi][q][2] * i254;
            float f3 = (float)acc1[mi][q][3] + (float)acc2[mi][q][3] * i254;
            float v0 = f0 * sa0 * sb_x, v1 = f1 * sa0 * sb_y;
            float v2 = f2 * sa8 * sb_x, v3 = f3 * sa8 * sb_y;
            if (EPI == 1) {
                const float2 u0 = *(const float2*)(OTH + o0);
                const float2 u1 = *(const float2*)(OTH + o1);
                v0 = u0.x * (v0 / (1.0f + expf(-v0)));
                v1 = u0.y * (v1 / (1.0f + expf(-v1)));
                v2 = u1.x * (v2 / (1.0f + expf(-v2)));
                v3 = u1.y * (v3 / (1.0f + expf(-v3)));
            }
            *(float2*)(Cf + o0) = make_float2(v0, v1);
            *(float2*)(Cf + o1) = make_float2(v2, v3);
        }
    }
}

// ===========================================================================
// scratch (static; no allocations).
// ===========================================================================
__device__ __nv_bfloat16 g_bf[805306368];   // 1.61 GB slab, used as int8
__device__ float g_c1[67108864];            // fp32 scratch A (256 MB)
__device__ float g_c2[67108864];            // fp32 scratch B (256 MB)
__device__ float g_sc[98304];               // row scales

// ---- row quantize: fp32 [R,C] -> 2x int8 slices + scale/row ----
__global__ void quantrow_k(const float* __restrict__ in, signed char* __restrict__ q1,
                           signed char* __restrict__ q0, float* __restrict__ s, int C) {
    const int r = blockIdx.x;
    const float* row = in + (size_t)r * C;
    float mx = 0.0f;
    for (int i = threadIdx.x; i < C; i += 256) mx = fmaxf(mx, fabsf(row[i]));
#pragma unroll
    for (int o = 16; o; o >>= 1) mx = fmaxf(mx, __shfl_xor_sync(0xFFFFFFFFu, mx, o));
    __shared__ float red[8];
    __shared__ float smx;
    if ((threadIdx.x & 31) == 0) red[threadIdx.x >> 5] = mx;
    __syncthreads();
    if (threadIdx.x == 0) {
        float m = red[0];
#pragma unroll
        for (int i = 1; i < 8; i++) m = fmaxf(m, red[i]);
        m = fmaxf(m, 1e-20f);
        smx = m;
        s[r] = m;
    }
    __syncthreads();
    const float inv = 127.0f / smx;
    for (int i = threadIdx.x; i < C; i += 256) {
        const float qv = row[i] * inv;
        const int i1 = __float2int_rn(qv);
        const int i0 = __float2int_rn((qv - (float)i1) * 254.0f);
        q1[(size_t)r * C + i] = (signed char)i1;
        q0[(size_t)r * C + i] = (signed char)i0;
    }
}
// fp32 transpose: in [R,C] -> out [C,R]
__global__ void tpose32_k(const float* __restrict__ in, float* __restrict__ out, int R, int C) {
    __shared__ float t[32][33];
    const int c0 = blockIdx.x * 32, r0 = blockIdx.y * 32;
#pragma unroll
    for (int i = 0; i < 32; i += 8)
        t[threadIdx.y + i][threadIdx.x] = in[(size_t)(r0 + threadIdx.y + i) * C + c0 + threadIdx.x];
    __syncthreads();
#pragma unroll
    for (int i = 0; i < 32; i += 8)
        out[(size_t)(c0 + threadIdx.y + i) * R + r0 + threadIdx.x] = t[threadIdx.x][threadIdx.y + i];
}

// ===========================================================================
typedef CUresult (*PFN_enc)(CUtensorMap*, CUtensorMapDataType, cuuint32_t, void*,
                            const cuuint64_t*, const cuuint64_t*, const cuuint32_t*,
                            const cuuint32_t*, CUtensorMapInterleave, CUtensorMapSwizzle,
                            CUtensorMapL2promotion, CUtensorMapFloatOOBfill);

static void enc_i8(PFN_enc fn, CUtensorMap* m, const signed char* p, int K, int rows) {
    cuuint64_t dims[3] = {(cuuint64_t)K, (cuuint64_t)rows, 1};
    cuuint64_t str[2] = {(cuuint64_t)K, (cuuint64_t)K * (cuuint64_t)rows};
    cuuint32_t box[3] = {64, 128, 1};
    cuuint32_t es[3] = {1, 1, 1};
    fn(m, CU_TENSOR_MAP_DATA_TYPE_UINT8, 3, (void*)p, dims, str, box, es,
       CU_TENSOR_MAP_INTERLEAVE_NONE, CU_TENSOR_MAP_SWIZZLE_64B,
       CU_TENSOR_MAP_L2_PROMOTION_L2_128B, CU_TENSOR_MAP_FLOAT_OOB_FILL_NONE);
}

static void rung(PFN_enc fn, int epi,
                 const signed char* A1, const signed char* A0,
                 const signed char* B1, const signed char* B0,
                 float* Cf, const float* OTH, const float* sA, const float* sB,
                 int M, int N, int K)
{
    CUtensorMap a1, a0, b1, b0;
    enc_i8(fn, &a1, A1, K, M);  enc_i8(fn, &a0, A0, K, M);
    enc_i8(fn, &b1, B1, K, N);  enc_i8(fn, &b0, B0, K, N);
    const dim3 g(N / 128, M / 128), b(512);
    if (epi == 0) {
        cudaFuncSetAttribute(gemm_i8<0>, cudaFuncAttributeMaxDynamicSharedMemorySize, SMEM_TOT);
        gemm_i8<0><<<g, b, SMEM_TOT>>>(a1, a0, b1, b0, Cf, OTH, sA, sB, M, N, K);
    } else {
        cudaFuncSetAttribute(gemm_i8<1>, cudaFuncAttributeMaxDynamicSharedMemorySize, SMEM_TOT);
        gemm_i8<1><<<g, b, SMEM_TOT>>>(a1, a0, b1, b0, Cf, OTH, sA, sB, M, N, K);
    }
}

extern "C" void kernel_launch(void* const* d_in, const int* in_sizes, int n_in,
                              void* d_out, int out_size)
{
    const float* x  = (const float*)d_in[0];
    const float* wu = (const float*)d_in[1];
    const float* wg = (const float*)d_in[2];
    const float* wd = (const float*)d_in[3];
    const float* h1 = (const float*)d_in[4];   // h_up_T   [F,F]
    const float* h2 = (const float*)d_in[5];   // h_gate_T [F,F]
    const float* h3 = (const float*)d_in[6];   // h_down   [F,F]

    int F = 1;
    while ((long long)(F + 1) * (F + 1) <= (long long)in_sizes[4]) F++;
    const int D = in_sizes[1] / F;
    const int M = in_sizes[0] / D;

    signed char* s8;
    float *C1, *C2, *SC;
    cudaGetSymbolAddress((void**)&s8, g_bf);
    cudaGetSymbolAddress((void**)&C1, g_c1);
    cudaGetSymbolAddress((void**)&C2, g_c2);
    cudaGetSymbolAddress((void**)&SC, g_sc);

    // int8 slab layout, 16M-element chunks
    const long long CH = 16777216LL;
    signed char *x1 = s8,            *x0 = s8 + CH;
    signed char *h1t1 = s8 + 2*CH,   *h1t0 = s8 + 6*CH;    // 64M each
    signed char *h2t1 = s8 + 10*CH,  *h2t0 = s8 + 14*CH;
    signed char *wut1 = s8 + 18*CH,  *wut0 = s8 + 19*CH;
    signed char *wgt1 = s8 + 20*CH,  *wgt0 = s8 + 21*CH;
    signed char *wd1  = s8 + 22*CH,  *wd0  = s8 + 23*CH;
    signed char *hd1  = s8 + 24*CH,  *hd0  = s8 + 28*CH;
    signed char *V11  = s8 + 32*CH,  *V10  = s8 + 33*CH;
    signed char *V21  = s8 + 34*CH,  *V20  = s8 + 35*CH;
    signed char *V31  = s8 + 36*CH,  *V30  = s8 + 37*CH;
    signed char *U1   = s8 + 38*CH,  *U0   = s8 + 42*CH;

    float *sx = SC, *sh1 = SC + 8192, *sh2 = SC + 16384, *swu = SC + 24576,
          *swg = SC + 32768, *swd = SC + 40960, *shd = SC + 49152,
          *sV1 = SC + 57344, *sV2 = SC + 65536, *sV3 = SC + 73728, *sU = SC + 81920;

    const dim3 tb(32, 8);
    const long long FD = (long long)F * D;

    // ---- prepass: transposes + row quantization ----
    quantrow_k<<<M, 256>>>(x, x1, x0, sx, D);
    tpose32_k<<<dim3(F / 32, F / 32), tb>>>(h1, C2, F, F);
    quantrow_k<<<F, 256>>>(C2, h1t1, h1t0, sh1, F);
    tpose32_k<<<dim3(F / 32, F / 32), tb>>>(h2, C2, F, F);
    quantrow_k<<<F, 256>>>(C2, h2t1, h2t0, sh2, F);
    tpose32_k<<<dim3(D / 32, F / 32), tb>>>(wu, C2, F, D);   // -> [D,F]
    quantrow_k<<<D, 256>>>(C2, wut1, wut0, swu, F);
    tpose32_k<<<dim3(D / 32, F / 32), tb>>>(wg, C2, F, D);
    quantrow_k<<<D, 256>>>(C2, wgt1, wgt0, swg, F);
    quantrow_k<<<D, 256>>>(wd, wd1, wd0, swd, F);
    quantrow_k<<<F, 256>>>(h3, hd1, hd0, shd, F);

    PFN_enc fn = nullptr;
    cudaDriverEntryPointQueryResult qr;
    cudaGetDriverEntryPoint("cuTensorMapEncodeTiled", (void**)&fn, cudaEnableDefault, &qr);

    // ---- fold GEMMs (fp32 out) ----
    // V1[F,D] = h1t @ wut^T
    rung(fn, 0, h1t1, h1t0, wut1, wut0, C1, nullptr, sh1, swu, F, D, F);
    // V2[F,D] = h2t @ wgt^T
    rung(fn, 0, h2t1, h2t0, wgt1, wgt0, C2, nullptr, sh2, swg, F, D, F);
    // V3[D,F] = wd @ hd^T
    rung(fn, 0, wd1, wd0, hd1, hd0, C1 + FD, nullptr, swd, shd, D, F, F);

    quantrow_k<<<F, 256>>>(C1, V11, V10, sV1, D);
    quantrow_k<<<F, 256>>>(C2, V21, V20, sV2, D);
    quantrow_k<<<D, 256>>>(C1 + FD, V31, V30, sV3, F);

    // ---- activation GEMMs ----
    // up2 = x @ V1^T -> C1 (fp32, full M*F)
    rung(fn, 0, x1, x0, V11, V10, C1, nullptr, sx, sV1, M, F, D);
    // gated = C1 * silu(x @ V2^T) -> C2
    rung(fn, 1, x1, x0, V21, V20, C2, C1, sx, sV2, M, F, D);
    quantrow_k<<<M, 256>>>(C2, U1, U0, sU, F);
    // out = U @ V3^T -> d_out
    rung(fn, 0, U1, U0, V31, V30, (float*)d_out, nullptr, sU, sV3, M, D, F);
}

// round 12
// speedup vs baseline: 3.5741x; 3.5741x over previous
#include <cuda_runtime.h>
#include <cuda.h>
#include <cuda_bf16.h>
#include <math.h>
#include <stdint.h>

// ===========================================================================
// R11: revert to R9 engine (bf16x3 mma.sync + TMA; best = 9383us), drop the
// V3-transpose detour: V3 computed directly [D,F] (split-write, full-K),
// V1/V2 batched z=4 split-K2 into fp32 partials + rsplit2.
// ===========================================================================

#define TILE_B 8192              // one 128x32 bf16 tile in smem (bytes)
#define STAGE_B 32768            // 4 tiles (Ah,Al,Bh,Bl)
#define SMEM_TOT (1024 + 1024 + 3 * STAGE_B)

__device__ __forceinline__ uint32_t smem_u32(const void* p) {
    uint32_t a;
    asm("{ .reg .u64 t; cvta.to.shared.u64 t, %1; cvt.u32.u64 %0, t; }" : "=r"(a) : "l"(p));
    return a;
}
#define MBARRIER_INIT(a, c) \
    asm volatile("mbarrier.init.shared.b64 [%0], %1;" :: "r"((uint32_t)(a)), "r"((uint32_t)(c)) : "memory")
#define MBARRIER_EXPECT_TX(a, b) \
    asm volatile("mbarrier.arrive.expect_tx.shared.b64 _, [%0], %1;" :: "r"((uint32_t)(a)), "r"((uint32_t)(b)) : "memory")
#define MBARRIER_WAIT_PARITY(a, p) do { \
    uint32_t _m = (uint32_t)(a), _p = (uint32_t)(p), _d; \
    asm volatile("{\n\t.reg .pred q;\n\t" \
        "mbarrier.try_wait.parity.acquire.cta.shared::cta.b64 q, [%1], %2;\n\t" \
        "selp.b32 %0, 1, 0, q;\n\t}" : "=r"(_d) : "r"(_m), "r"(_p) : "memory"); \
    if (!_d) { \
        asm volatile("{\n\t.reg .pred Q;\n\t" \
            "WL_%=:\n\t" \
            "mbarrier.try_wait.parity.acquire.cta.shared::cta.b64 Q, [%0], %1, 0x989680;\n\t" \
            "@Q bra.uni WD_%=;\n\t" \
            "bra.uni WL_%=;\n\t" \
            "WD_%=:\n\t}" :: "r"(_m), "r"(_p) : "memory"); \
    } \
} while (0)
#define TMA_LOAD_3D(sa, tm, cx, cy, cz, mb) \
    asm volatile("cp.async.bulk.tensor.3d.shared::cta.global.tile.mbarrier::complete_tx::bytes " \
        "[%0], [%1, {%2, %3, %4}], [%5];" \
        :: "r"((uint32_t)(sa)), "l"(tm), "r"((int32_t)(cx)), "r"((int32_t)(cy)), \
           "r"((int32_t)(cz)), "r"((uint32_t)(mb)) : "memory")
#define LDSM4(R, a) \
    asm volatile("ldmatrix.sync.aligned.m8n8.x4.shared.b16 {%0,%1,%2,%3}, [%4];" \
        : "=r"((R)[0]), "=r"((R)[1]), "=r"((R)[2]), "=r"((R)[3]) : "r"(a))

__device__ __forceinline__ void mma_bf16(float* c, const uint32_t* a, uint32_t b0, uint32_t b1) {
    asm volatile(
        "mma.sync.aligned.m16n8k16.row.col.f32.bf16.bf16.f32 "
        "{%0,%1,%2,%3}, {%4,%5,%6,%7}, {%8,%9}, {%0,%1,%2,%3};"
        : "+f"(c[0]), "+f"(c[1]), "+f"(c[2]), "+f"(c[3])
        : "r"(a[0]), "r"(a[1]), "r"(a[2]), "r"(a[3]), "r"(b0), "r"(b1));
}

// 16B XOR swizzle within a [rows x 32] bf16 tile (== TMA SWIZZLE_64B).
__device__ __forceinline__ uint32_t sw(int row, int col16) {
    return (uint32_t)(row * 64 + ((col16 ^ ((row >> 1) & 3)) << 4));
}

// EPI 1: fp32 write Cf.   EPI 2: v = OTH*silu(acc), split-write Ch/Cl.
// EPI 3: z==0 split-write Ch/Cl full-K (used with zmode 2, gz=1).
// zmode 0: z = batch coord.   zmode 1: split-K (k0 = z*kz, Cf += z*czs).
// zmode 2: z0 = full-K split-write batch0.   zmode 3: z -> (batch z>>1, K-half z&1).
template <int EPI>
__global__ __launch_bounds__(256, 2) void gemm_b3(
    const __grid_constant__ CUtensorMap tAh, const __grid_constant__ CUtensorMap tAl,
    const __grid_constant__ CUtensorMap tBh, const __grid_constant__ CUtensorMap tBl,
    float* __restrict__ Cf, __nv_bfloat16* __restrict__ Ch, __nv_bfloat16* __restrict__ Cl,
    const float* __restrict__ OTH, int M, int N, int K,
    long long czs, int kz, int zmode)
{
    extern __shared__ char smem[];
    const uint32_t sb0 = smem_u32(smem);
    const uint32_t sb = (sb0 + 1023) & ~1023u;
    const int tid = threadIdx.x;
    const int z = blockIdx.z;

    int cz, k00, Keff;
    bool splitout = false;
    if (zmode == 1) {
        cz = 0; k00 = z * kz; Keff = kz;
        Cf += (size_t)z * czs;
    } else if (zmode == 2) {
        cz = 0; k00 = 0; Keff = K; splitout = true;
    } else if (zmode == 3) {
        cz = z >> 1; k00 = (z & 1) * kz; Keff = kz;
        Cf += (size_t)z * czs;
    } else {
        cz = z; k00 = 0; Keff = K;
        if (Cf) Cf += (size_t)z * czs;
        if (Ch) { Ch += (size_t)z * czs; Cl += (size_t)z * czs; }
    }

    // ---- L2-friendly CTA rasterization (GROUP_M = 16), per z-slice ----
    const int gn = gridDim.x, gm = gridDim.y;
    const int bid = blockIdx.y * gn + blockIdx.x;
    const int npg = 16 * gn;
    const int gid = bid / npg;
    const int fm = gid * 16;
    const int gs = (gm - fm < 16) ? (gm - fm) : 16;
    const int bm = (fm + (bid % gs)) * 128;
    const int bn = ((bid % npg) / gs) * 128;

    const int w = tid >> 5, lane = tid & 31;
    const int wm = (w >> 2) * 64, wn = (w & 3) * 32;
    const int jj = lane >> 3, rr = lane & 7;
    const int aR = (jj & 1) * 8 + rr, aC16 = jj >> 1;
    const int bR = (jj >> 1) * 8 + rr, bC16 = jj & 1;

    const uint32_t bars = sb;
    const uint32_t stg0 = sb + 1024;

    if (tid == 0) {
        MBARRIER_INIT(bars + 0, 1);
        MBARRIER_INIT(bars + 8, 1);
        MBARRIER_INIT(bars + 16, 1);
    }
    __syncthreads();

    const int nst = Keff / 32;

    if (tid == 0) {
#pragma unroll
        for (int s = 0; s < 3; s++) {
            const uint32_t bar = bars + s * 8;
            const uint32_t stb = stg0 + s * STAGE_B;
            const int k0 = k00 + s * 32;
            MBARRIER_EXPECT_TX(bar, STAGE_B);
            TMA_LOAD_3D(stb,              &tAh, k0, bm, cz, bar);
            TMA_LOAD_3D(stb + TILE_B,     &tAl, k0, bm, cz, bar);
            TMA_LOAD_3D(stb + 2 * TILE_B, &tBh, k0, bn, cz, bar);
            TMA_LOAD_3D(stb + 3 * TILE_B, &tBl, k0, bn, cz, bar);
        }
    }

    float c[4][4][4];
#pragma unroll
    for (int mi = 0; mi < 4; mi++)
#pragma unroll
        for (int ni = 0; ni < 4; ni++)
#pragma unroll
            for (int q = 0; q < 4; q++) c[mi][ni][q] = 0.0f;

    for (int t = 0; t < nst; t++) {
        const int buf = t % 3;
        MBARRIER_WAIT_PARITY(bars + buf * 8, (t / 3) & 1);

        const uint32_t stb = stg0 + (uint32_t)buf * STAGE_B;
#pragma unroll
        for (int ks = 0; ks < 2; ks++) {
            uint32_t af[4][4], bhf[2][4], blf[2][4];
#pragma unroll
            for (int mi = 0; mi < 4; mi++)
                LDSM4(af[mi], stb + sw(wm + mi * 16 + aR, ks * 2 + aC16));
#pragma unroll
            for (int np = 0; np < 2; np++) {
                const uint32_t bd = stb + 2 * TILE_B + sw(wn + np * 16 + bR, ks * 2 + bC16);
                LDSM4(bhf[np], bd);
                LDSM4(blf[np], bd + TILE_B);
            }
#pragma unroll
            for (int mi = 0; mi < 4; mi++)
#pragma unroll
                for (int ni = 0; ni < 4; ni++) {
                    const int p = ni >> 1, q = (ni & 1) * 2;
                    mma_bf16(c[mi][ni], af[mi], bhf[p][q], bhf[p][q + 1]);
                    mma_bf16(c[mi][ni], af[mi], blf[p][q], blf[p][q + 1]);
                }
#pragma unroll
            for (int mi = 0; mi < 4; mi++)
                LDSM4(af[mi], stb + TILE_B + sw(wm + mi * 16 + aR, ks * 2 + aC16));
#pragma unroll
            for (int mi = 0; mi < 4; mi++)
#pragma unroll
                for (int ni = 0; ni < 4; ni++) {
                    const int p = ni >> 1, q = (ni & 1) * 2;
                    mma_bf16(c[mi][ni], af[mi], bhf[p][q], bhf[p][q + 1]);
                }
        }

        __syncthreads();
        if (t + 3 < nst && tid == 0) {
            const uint32_t bar = bars + buf * 8;
            const int k0 = k00 + (t + 3) * 32;
            MBARRIER_EXPECT_TX(bar, STAGE_B);
            TMA_LOAD_3D(stb,              &tAh, k0, bm, cz, bar);
            TMA_LOAD_3D(stb + TILE_B,     &tAl, k0, bm, cz, bar);
            TMA_LOAD_3D(stb + 2 * TILE_B, &tBh, k0, bn, cz, bar);
            TMA_LOAD_3D(stb + 3 * TILE_B, &tBl, k0, bn, cz, bar);
        }
    }

    // ---- epilogue ----
#pragma unroll
    for (int mi = 0; mi < 4; mi++)
#pragma unroll
        for (int ni = 0; ni < 4; ni++) {
            const int r0 = bm + wm + mi * 16 + (lane >> 2);
            const int col = bn + wn + ni * 8 + (lane & 3) * 2;
            const size_t o0 = (size_t)r0 * N + col;
            const size_t o1 = (size_t)(r0 + 8) * N + col;
            float v0 = c[mi][ni][0], v1 = c[mi][ni][1];
            float v2 = c[mi][ni][2], v3 = c[mi][ni][3];
            if (EPI == 2) {
                const float2 u0 = *(const float2*)(OTH + o0);
                const float2 u1 = *(const float2*)(OTH + o1);
                v0 = u0.x * (v0 / (1.0f + expf(-v0)));
                v1 = u0.y * (v1 / (1.0f + expf(-v1)));
                v2 = u1.x * (v2 / (1.0f + expf(-v2)));
                v3 = u1.y * (v3 / (1.0f + expf(-v3)));
            }
            const bool wr_split = (EPI == 2) || (EPI == 3 && splitout);
            if (wr_split) {
                __nv_bfloat162 hh, ll;
                hh.x = __float2bfloat16(v0); hh.y = __float2bfloat16(v1);
                ll.x = __float2bfloat16(v0 - __bfloat162float(hh.x));
                ll.y = __float2bfloat16(v1 - __bfloat162float(hh.y));
                *(__nv_bfloat162*)(Ch + o0) = hh;
                *(__nv_bfloat162*)(Cl + o0) = ll;
                hh.x = __float2bfloat16(v2); hh.y = __float2bfloat16(v3);
                ll.x = __float2bfloat16(v2 - __bfloat162float(hh.x));
                ll.y = __float2bfloat16(v3 - __bfloat162float(hh.y));
                *(__nv_bfloat162*)(Ch + o1) = hh;
                *(__nv_bfloat162*)(Cl + o1) = ll;
            } else {
                *(float2*)(Cf + o0) = make_float2(v0, v1);
                *(float2*)(Cf + o1) = make_float2(v2, v3);
            }
        }
}

// ===========================================================================
// scratch (static; no allocations).
// ===========================================================================
#define MDE 16777216ll
#define FFE 67108864ll
__device__ __nv_bfloat16 g_bf[805306368];   // 16 MDE + 8 FFE exactly
__device__ float g_c1[67108864];

// ---- pre-pass: fp32 -> (bf16 hi, bf16 lo) ----
struct bf4 { __nv_bfloat162 a, b; };
__global__ void split_k(const float4* __restrict__ in, bf4* __restrict__ hi,
                        bf4* __restrict__ lo, int n4) {
    for (int i = blockIdx.x * blockDim.x + threadIdx.x; i < n4; i += gridDim.x * blockDim.x) {
        const float4 v = in[i];
        bf4 H, L;
        H.a.x = __float2bfloat16(v.x); H.a.y = __float2bfloat16(v.y);
        H.b.x = __float2bfloat16(v.z); H.b.y = __float2bfloat16(v.w);
        L.a.x = __float2bfloat16(v.x - __bfloat162float(H.a.x));
        L.a.y = __float2bfloat16(v.y - __bfloat162float(H.a.y));
        L.b.x = __float2bfloat16(v.z - __bfloat162float(H.b.x));
        L.b.y = __float2bfloat16(v.w - __bfloat162float(H.b.y));
        hi[i] = H; lo[i] = L;
    }
}
// transpose + split with 128B paired stores: in [R,C] fp32 -> out [C,R] bf16 pair
__global__ void tsplit_k(const float* __restrict__ in, __nv_bfloat16* __restrict__ hi,
                         __nv_bfloat16* __restrict__ lo, int R, int C) {
    __shared__ float t[64][33];
    const int c0 = blockIdx.x * 32, r0 = blockIdx.y * 64;
#pragma unroll
    for (int i = 0; i < 8; i++) {
        const int row = threadIdx.y + i * 8;
        t[row][threadIdx.x] = in[(size_t)(r0 + row) * C + c0 + threadIdx.x];
    }
    __syncthreads();
#pragma unroll
    for (int j = 0; j < 4; j++) {
        const int cc = threadIdx.y + j * 8;
        const int rr = threadIdx.x * 2;
        const float v0 = t[rr][cc], v1 = t[rr + 1][cc];
        __nv_bfloat162 hh, ll;
        hh.x = __float2bfloat16(v0); hh.y = __float2bfloat16(v1);
        ll.x = __float2bfloat16(v0 - __bfloat162float(hh.x));
        ll.y = __float2bfloat16(v1 - __bfloat162float(hh.y));
        const size_t o = (size_t)(c0 + cc) * R + r0 + rr;
        *(__nv_bfloat162*)(hi + o) = hh;
        *(__nv_bfloat162*)(lo + o) = ll;
    }
}
// reduce 2 K-half partials and split -> V_b (b = blockIdx.y in {0,1})
__global__ void rsplit2_k(const float4* __restrict__ p, bf4* __restrict__ vh,
                          bf4* __restrict__ vl, int n4) {
    const int b = blockIdx.y;
    const float4* pa = p + (size_t)b * 2 * n4;
    bf4* oh = vh + (size_t)b * 2 * n4;
    bf4* ol = vl + (size_t)b * 2 * n4;
    for (int i = blockIdx.x * blockDim.x + threadIdx.x; i < n4; i += gridDim.x * blockDim.x) {
        const float4 x = pa[i], y = pa[i + n4];
        const float4 s = make_float4(x.x + y.x, x.y + y.y, x.z + y.z, x.w + y.w);
        bf4 H, L;
        H.a.x = __float2bfloat16(s.x); H.a.y = __float2bfloat16(s.y);
        H.b.x = __float2bfloat16(s.z); H.b.y = __float2bfloat16(s.w);
        L.a.x = __float2bfloat16(s.x - __bfloat162float(H.a.x));
        L.a.y = __float2bfloat16(s.y - __bfloat162float(H.a.y));
        L.b.x = __float2bfloat16(s.z - __bfloat162float(H.b.x));
        L.b.y = __float2bfloat16(s.w - __bfloat162float(H.b.y));
        oh[i] = H; ol[i] = L;
    }
}
// reduce 4 split-K partials (fixed order, deterministic)
__global__ void red4_k(const float4* __restrict__ p, float4* __restrict__ o, int n4) {
    for (int i = blockIdx.x * blockDim.x + threadIdx.x; i < n4; i += gridDim.x * blockDim.x) {
        const float4 a = p[i], b = p[i + n4], c = p[i + 2 * n4], d = p[i + 3 * n4];
        o[i] = make_float4(((a.x + b.x) + c.x) + d.x, ((a.y + b.y) + c.y) + d.y,
                           ((a.z + b.z) + c.z) + d.z, ((a.w + b.w) + c.w) + d.w);
    }
}

// ===========================================================================
typedef CUresult (*PFN_enc)(CUtensorMap*, CUtensorMapDataType, cuuint32_t, void*,
                            const cuuint64_t*, const cuuint64_t*, const cuuint32_t*,
                            const cuuint32_t*, CUtensorMapInterleave, CUtensorMapSwizzle,
                            CUtensorMapL2promotion, CUtensorMapFloatOOBfill);

static void enc_map(PFN_enc fn, CUtensorMap* m, const __nv_bfloat16* p, int K, int rows,
                    int nz, long long zelems) {
    cuuint64_t dims[3] = {(cuuint64_t)K, (cuuint64_t)rows, (cuuint64_t)nz};
    cuuint64_t str[2] = {(cuuint64_t)K * 2, (cuuint64_t)zelems * 2};
    cuuint32_t box[3] = {32, 128, 1};
    cuuint32_t es[3] = {1, 1, 1};
    fn(m, CU_TENSOR_MAP_DATA_TYPE_BFLOAT16, 3, (void*)p, dims, str, box, es,
       CU_TENSOR_MAP_INTERLEAVE_NONE, CU_TENSOR_MAP_SWIZZLE_64B,
       CU_TENSOR_MAP_L2_PROMOTION_L2_128B, CU_TENSOR_MAP_FLOAT_OOB_FILL_NONE);
}

static void rung(PFN_enc fn, int epi,
                 const __nv_bfloat16* Ah, const __nv_bfloat16* Al,
                 const __nv_bfloat16* Bh, const __nv_bfloat16* Bl,
                 float* Cf, __nv_bfloat16* Ch, __nv_bfloat16* Cl,
                 const float* OTH, int M, int N, int K,
                 int nz, long long zsA, long long zsB, long long czs,
                 int kz, int zmode, int gz)
{
    CUtensorMap ma, mal, mb, mbl;
    enc_map(fn, &ma, Ah, K, M, nz, zsA);  enc_map(fn, &mal, Al, K, M, nz, zsA);
    enc_map(fn, &mb, Bh, K, N, nz, zsB);  enc_map(fn, &mbl, Bl, K, N, nz, zsB);
    const dim3 g(N / 128, M / 128, gz), b(256);
    if (epi == 1) {
        cudaFuncSetAttribute(gemm_b3<1>, cudaFuncAttributeMaxDynamicSharedMemorySize, SMEM_TOT);
        gemm_b3<1><<<g, b, SMEM_TOT>>>(ma, mal, mb, mbl, Cf, Ch, Cl, OTH, M, N, K, czs, kz, zmode);
    } else if (epi == 2) {
        cudaFuncSetAttribute(gemm_b3<2>, cudaFuncAttributeMaxDynamicSharedMemorySize, SMEM_TOT);
        gemm_b3<2><<<g, b, SMEM_TOT>>>(ma, mal, mb, mbl, Cf, Ch, Cl, OTH, M, N, K, czs, kz, zmode);
    } else {
        cudaFuncSetAttribute(gemm_b3<3>, cudaFuncAttributeMaxDynamicSharedMemorySize, SMEM_TOT);
        gemm_b3<3><<<g, b, SMEM_TOT>>>(ma, mal, mb, mbl, Cf, Ch, Cl, OTH, M, N, K, czs, kz, zmode);
    }
}

extern "C" void kernel_launch(void* const* d_in, const int* in_sizes, int n_in,
                              void* d_out, int out_size)
{
    const float* x  = (const float*)d_in[0];
    const float* wu = (const float*)d_in[1];
    const float* wg = (const float*)d_in[2];
    const float* wd = (const float*)d_in[3];
    const float* h1 = (const float*)d_in[4];   // h_up_T   [F,F]
    const float* h2 = (const float*)d_in[5];   // h_gate_T [F,F]
    const float* h3 = (const float*)d_in[6];   // h_down   [F,F]

    int F = 1;
    while ((long long)(F + 1) * (F + 1) <= (long long)in_sizes[4]) F++;
    const int D = in_sizes[1] / F;
    const int M = in_sizes[0] / D;

    __nv_bfloat16* bb;
    float* C1;
    cudaGetSymbolAddress((void**)&bb, g_bf);
    cudaGetSymbolAddress((void**)&C1, g_c1);

    // slab layout (16 MDE + 8 FFE, exact fit)
    __nv_bfloat16 *xh   = bb,             *xl   = bb + MDE;
    __nv_bfloat16 *wdh  = bb + 2 * MDE,   *wuth = bb + 3 * MDE,  *wgth = bb + 4 * MDE;
    __nv_bfloat16 *wdl  = bb + 5 * MDE,   *wutl = bb + 6 * MDE,  *wgtl = bb + 7 * MDE;
    __nv_bfloat16 *V1h  = bb + 8 * MDE,   *V1l  = bb + 9 * MDE;
    __nv_bfloat16 *V2h  = bb + 10 * MDE,  *V2l  = bb + 11 * MDE;
    __nv_bfloat16 *V3h  = bb + 12 * MDE,  *V3l  = bb + 13 * MDE;   // V3 [D,F]
    __nv_bfloat16* hb   = bb + 16 * MDE;
    __nv_bfloat16 *hdh  = hb,             *h1th = hb + FFE,      *h2th = hb + 2 * FFE;
    __nv_bfloat16 *hdl  = hb + 3 * FFE,   *h1tl = hb + 4 * FFE,  *h2tl = hb + 5 * FFE;
    __nv_bfloat16 *Uh   = hb + 6 * FFE,   *Ul   = hb + 7 * FFE;

    // ---- prepass ----
    split_k<<<2048, 256>>>((const float4*)x,  (bf4*)xh,  (bf4*)xl,  (M * D) / 4);
    split_k<<<2048, 256>>>((const float4*)wd, (bf4*)wdh, (bf4*)wdl, (D * F) / 4);
    split_k<<<2048, 256>>>((const float4*)h3, (bf4*)hdh, (bf4*)hdl, (F * F) / 4);
    const dim3 tb(32, 8);
    tsplit_k<<<dim3(F / 32, F / 64), tb>>>(h1, h1th, h1tl, F, F);
    tsplit_k<<<dim3(F / 32, F / 64), tb>>>(h2, h2th, h2tl, F, F);
    tsplit_k<<<dim3(D / 32, F / 64), tb>>>(wu, wuth, wutl, F, D);
    tsplit_k<<<dim3(D / 32, F / 64), tb>>>(wg, wgth, wgtl, F, D);

    PFN_enc fn = nullptr;
    cudaDriverEntryPointQueryResult qr;
    cudaGetDriverEntryPoint("cuTensorMapEncodeTiled", (void**)&fn, cudaEnableDefault, &qr);

    const long long FD = (long long)F * D;

    // ---- V3[D,F] = wd @ hd^T, full-K, direct split-write (no transpose) ----
    rung(fn, 3, wdh, wdl, hdh, hdl, nullptr, V3h, V3l, nullptr,
         D, F, F, 1, 0, 0, 0, 0, 2, 1);

    // ---- V1/V2 batched z=4: (batch z>>1) x (K-half z&1) -> fp32 partials in C1 ----
    // A planes [h1t][h2t] stride FFE; B planes [wut][wgt] stride MDE.
    rung(fn, 1, h1th, h1tl, wuth, wutl, C1, nullptr, nullptr, nullptr,
         F, D, F, 2, FFE, MDE, FD, F / 2, 3, 4);

    // V1 = p0+p1, V2 = p2+p3 (split-write)
    rsplit2_k<<<dim3(2048, 2), 256>>>((const float4*)C1, (bf4*)V1h, (bf4*)V1l, (int)(FD / 4));

    // ---- activation GEMMs ----
    // up2 = x @ V1^T -> C1 (fp32)
    rung(fn, 1, xh, xl, V1h, V1l, C1, nullptr, nullptr, nullptr,
         M, F, D, 1, MDE, MDE, 0, 0, 0, 1);
    // gated = C1 * silu(x @ V2^T) -> split U
    rung(fn, 2, xh, xl, V2h, V2l, nullptr, Uh, Ul, C1,
         M, F, D, 1, MDE, MDE, 0, 0, 0, 1);
    // out = gated @ V3^T, split-K4 -> partials in C1, then deterministic reduce
    rung(fn, 1, Uh, Ul, V3h, V3l, C1, nullptr, nullptr, nullptr,
         M, D, F, 1, FFE, MDE, (long long)M * D, F / 4, 1, 4);
    red4_k<<<2048, 256>>>((const float4*)C1, (float4*)d_out, (M * D) / 4);
}